// round 10
// baseline (speedup 1.0000x reference)
#include <cuda_runtime.h>

#define NSEG 2048
#define NB1 2048       // level-1: top 11 bits of float pattern
#define NB2 4096       // level-2: bits [20:9]
#define NB3 512        // level-3: bits [8:0]
#define CANDMAX 262144
#define STAGECAP 1024
#define NMAX 4000000

#define ALPHA 0.1f
#define BETA  0.1f
#define CAPACITY 1000.0f
#define INV2P30 9.313225746154785e-10   // 2^-30 exact

// ---------------- device scratch (zero-init at load; leave-clean protocol:
// every buffer is reset to zero by its LAST consumer each replay) ----------
__device__ double g_sum_nllw;
__device__ double g_sum_w;
__device__ float g_cnt[NSEG];
__device__ float g_psum[NSEG];
__device__ float g_rate[NSEG];
__device__ float g_dws[NSEG];
__device__ unsigned g_h1[NB1];
__device__ unsigned g_h2a[NB2];
__device__ unsigned g_h2b[NB2];
__device__ unsigned g_h3a[NB3];
__device__ unsigned g_h3b[NB3];
__device__ unsigned g_candA[CANDMAX];
__device__ unsigned g_candB[CANDMAX];
__device__ unsigned g_ccA, g_ccB;
__device__ __align__(16) float g_dobs[NMAX];
__device__ unsigned g_selL1[4];   // {bin1Lo, remLo, bin1Hi, remHi}
__device__ unsigned g_selL2[4];   // {mid12Lo, remLo2, mid12Hi, remHi2}
__device__ float g_frac;
__device__ unsigned g_nvalid;
__device__ unsigned g_done1, g_done2, g_done3;

// ---------------- per-row work (inlined 4x in the quad loop) ---------------
__device__ __forceinline__ float row_op(
    float l0, float l1, int yi, int m, int w,
    float dx, float rx, float cw0, float cw1,
    float& acc_nllw, float& acc_w,
    unsigned long long* s_cps, float* s_rt, float* s_dw, unsigned* s_h1)
{
    float mx = fmaxf(l0, l1);
    float e0 = __expf(l0 - mx);
    float e1 = __expf(l1 - mx);
    float se = e0 + e1;
    float nll = mx + __logf(se) - (yi ? l1 : l0);
    float wyv = (yi ? cw1 : cw0) * (m ? 1.0f : 0.0f);
    acc_nllw += nll * wyv;
    acc_w += wyv;
    float p = e1 / se;
    bool valid = (m != 0) && (w >= 0);
    float dobs = fmaxf(dx, 0.0f);
    float rate = fmaxf(rx, 0.0f);
    if (valid) {
        // cnt in bits [48:64), psum fixed-point 2^30 in [0:48): carry-free
        unsigned long long pk = (1ull << 48) +
            (unsigned long long)(p * 1073741824.0f);
        atomicAdd(&s_cps[w], pk);
        atomicAdd(&s_rt[w], p * rate);
        atomicAdd(&s_dw[w], p * dobs);
        unsigned ub = __float_as_uint(dobs) >> 21;
        // bin 0 (exact zeros) reconstructed as nvalid - sum(bins>=1)
        if (ub) atomicAdd(&s_h1[ub], 1u);
        return dobs;
    }
    return __uint_as_float(0xFFFFFFFFu);
}

// ---------------- pass1: fused CE + segments + L1-hist + dobs + sel1 -------
__global__ void __launch_bounds__(512, 3) pass1_kernel(
    const float4* __restrict__ logits4,
    const int4* __restrict__ y4,
    const int4* __restrict__ m4,
    const float* __restrict__ xraw,
    const int4* __restrict__ w4,
    const float* __restrict__ cw,
    int n)
{
    __shared__ unsigned long long s_cps[NSEG];  // 16KB: cnt|psum packed
    __shared__ float s_rt[NSEG];                // 8KB
    __shared__ float s_dw[NSEG];                // 8KB
    __shared__ unsigned s_h1[NB1];              // 8KB
    __shared__ float s_red[32];
    __shared__ unsigned s_scan[512];
    __shared__ float s_totalf;
    __shared__ int s_last;

    int tid = threadIdx.x;
    int lane = tid & 31;
    for (int i = tid; i < NSEG; i += blockDim.x) {
        s_cps[i] = 0ull; s_rt[i] = 0.0f; s_dw[i] = 0.0f; s_h1[i] = 0u;
    }
    __syncthreads();

    const float cw0 = __ldg(&cw[0]);
    const float cw1 = __ldg(&cw[1]);

    float acc_nllw = 0.0f, acc_w = 0.0f;

    int nquad = n >> 2;
    int gstride = gridDim.x * blockDim.x;
    float4* dobs4 = reinterpret_cast<float4*>(g_dobs);
    for (int j = blockIdx.x * blockDim.x + tid; j < nquad; j += gstride) {
        int i0 = j << 2;
        float4 lgA = logits4[2 * j];
        float4 lgB = logits4[2 * j + 1];
        int4 yy = y4[j];
        int4 mm = m4[j];
        int4 ww = w4[j];
        float2 x0 = *reinterpret_cast<const float2*>(xraw + (size_t)i0 * 8 + 2);
        float2 x1 = *reinterpret_cast<const float2*>(xraw + (size_t)(i0 + 1) * 8 + 2);
        float2 x2 = *reinterpret_cast<const float2*>(xraw + (size_t)(i0 + 2) * 8 + 2);
        float2 x3 = *reinterpret_cast<const float2*>(xraw + (size_t)(i0 + 3) * 8 + 2);

        float4 st;
        st.x = row_op(lgA.x, lgA.y, yy.x, mm.x, ww.x, x0.x, x0.y, cw0, cw1,
                      acc_nllw, acc_w, s_cps, s_rt, s_dw, s_h1);
        st.y = row_op(lgA.z, lgA.w, yy.y, mm.y, ww.y, x1.x, x1.y, cw0, cw1,
                      acc_nllw, acc_w, s_cps, s_rt, s_dw, s_h1);
        st.z = row_op(lgB.x, lgB.y, yy.z, mm.z, ww.z, x2.x, x2.y, cw0, cw1,
                      acc_nllw, acc_w, s_cps, s_rt, s_dw, s_h1);
        st.w = row_op(lgB.z, lgB.w, yy.w, mm.w, ww.w, x3.x, x3.y, cw0, cw1,
                      acc_nllw, acc_w, s_cps, s_rt, s_dw, s_h1);
        dobs4[j] = st;
    }

    // tail rows (n % 4)
    if (blockIdx.x == 0 && tid == 0) {
        const float* lgs = reinterpret_cast<const float*>(logits4);
        const int* ys = reinterpret_cast<const int*>(y4);
        const int* ms = reinterpret_cast<const int*>(m4);
        const int* ws = reinterpret_cast<const int*>(w4);
        for (int i = nquad << 2; i < n; i++) {
            float2 x23 = *reinterpret_cast<const float2*>(xraw + (size_t)i * 8 + 2);
            g_dobs[i] = row_op(lgs[2 * i], lgs[2 * i + 1], ys[i], ms[i], ws[i],
                               x23.x, x23.y, cw0, cw1,
                               acc_nllw, acc_w, s_cps, s_rt, s_dw, s_h1);
        }
    }

    // CE block reduce
    #pragma unroll
    for (int o = 16; o > 0; o >>= 1) {
        acc_nllw += __shfl_down_sync(0xFFFFFFFFu, acc_nllw, o);
        acc_w    += __shfl_down_sync(0xFFFFFFFFu, acc_w, o);
    }
    int warp = tid >> 5;
    if (lane == 0) { s_red[warp] = acc_nllw; s_red[warp + 16] = acc_w; }
    __syncthreads();
    if (tid == 0) {
        float a = 0.0f, b = 0.0f;
        for (int k = 0; k < 16; k++) { a += s_red[k]; b += s_red[k + 16]; }
        atomicAdd(&g_sum_nllw, (double)a);
        atomicAdd(&g_sum_w, (double)b);
    }

    // flush segment bins + level-1 histogram
    for (int i = tid; i < NSEG; i += blockDim.x) {
        unsigned long long wd = s_cps[i];
        if (wd) {
            float cnt = (float)(unsigned)(wd >> 48);
            float ps = (float)((double)(wd & 0xFFFFFFFFFFFFull) * INV2P30);
            atomicAdd(&g_cnt[i], cnt);
            atomicAdd(&g_psum[i], ps);
            atomicAdd(&g_rate[i], s_rt[i]);
            atomicAdd(&g_dws[i], s_dw[i]);
        }
        unsigned h = s_h1[i];
        if (h) atomicAdd(&g_h1[i], h);
    }

    // ---- last-block: sel1 ----
    __syncthreads();
    __threadfence();
    if (tid == 0) s_last = (atomicAdd(&g_done1, 1u) == gridDim.x - 1u) ? 1 : 0;
    __syncthreads();
    if (!s_last) return;
    __threadfence();

    // total valid = sum of g_cnt (exact: integer counts in fp32)
    float csum = 0.0f;
    #pragma unroll
    for (int j = 0; j < 4; j++) csum += g_cnt[tid * 4 + j];
    #pragma unroll
    for (int o = 16; o > 0; o >>= 1) csum += __shfl_down_sync(0xFFFFFFFFu, csum, o);
    if (lane == 0) s_red[warp] = csum;
    __syncthreads();
    if (tid == 0) {
        float t = 0.0f;
        for (int k = 0; k < 16; k++) t += s_red[k];
        s_totalf = t;
    }
    __syncthreads();
    unsigned nvalid = __float2uint_rn(s_totalf);

    // scan of bins >=1 (g_h1[0] is always 0)
    unsigned base = (unsigned)tid * 4;
    unsigned h[4];
    unsigned s = 0;
    #pragma unroll
    for (int j = 0; j < 4; j++) { h[j] = g_h1[base + j]; s += h[j]; }
    // leave-clean: reset h1 for next replay (values held in regs)
    #pragma unroll
    for (int j = 0; j < 4; j++) g_h1[base + j] = 0u;
    s_scan[tid] = s;
    __syncthreads();
    for (int off = 1; off < 512; off <<= 1) {
        unsigned v = (tid >= off) ? s_scan[tid - off] : 0u;
        __syncthreads();
        s_scan[tid] += v;
        __syncthreads();
    }
    unsigned S_rest = s_scan[511];
    unsigned bin0 = nvalid - S_rest;

    float nf = (float)nvalid;
    float pos = fmaxf(0.75f * (nf - 1.0f), 0.0f);
    float fl = floorf(pos);
    unsigned rlo = (unsigned)fl;
    unsigned rhi = (unsigned)ceilf(pos);
    if (tid == 0) {
        g_frac = pos - fl;
        g_nvalid = nvalid;
        g_done1 = 0u;   // leave-clean
        if (nvalid > 0 && rlo < bin0) { g_selL1[0] = 0u; g_selL1[1] = rlo; }
        if (nvalid > 0 && rhi < bin0) { g_selL1[2] = 0u; g_selL1[3] = rhi; }
    }

    unsigned c = bin0 + s_scan[tid] - s;
    #pragma unroll
    for (int j = 0; j < 4; j++) {
        if (h[j]) {
            if (rlo >= c && rlo < c + h[j]) { g_selL1[0] = base + j; g_selL1[1] = rlo - c; }
            if (rhi >= c && rhi < c + h[j]) { g_selL1[2] = base + j; g_selL1[3] = rhi - c; }
        }
        c += h[j];
    }
}

// ---------------- sel2 scan helper (512 threads, 4096 bins) ----------------
__device__ void sel2_find(const unsigned* __restrict__ hist, unsigned rank,
                          unsigned* s_scan, unsigned* gres) {
    int t = threadIdx.x;
    unsigned base = (unsigned)t * 8;
    unsigned h[8];
    unsigned s = 0;
    #pragma unroll
    for (int j = 0; j < 8; j++) { h[j] = hist[base + j]; s += h[j]; }
    s_scan[t] = s;
    __syncthreads();
    for (int off = 1; off < 512; off <<= 1) {
        unsigned v = (t >= off) ? s_scan[t - off] : 0u;
        __syncthreads();
        s_scan[t] += v;
        __syncthreads();
    }
    unsigned c = s_scan[t] - s;
    #pragma unroll
    for (int j = 0; j < 8; j++) {
        if (h[j] && rank >= c && rank < c + h[j]) {
            gres[0] = base + j;
            gres[1] = rank - c;
        }
        c += h[j];
    }
    __syncthreads();
}

// ---------------- lvl2: mid-12-bit hist + candidates, fused sel2 -----------
__global__ void __launch_bounds__(512) lvl2_kernel(int n) {
    __shared__ unsigned sa[NB2];
    __shared__ unsigned sb[NB2];
    __shared__ unsigned stgA[STAGECAP];
    __shared__ unsigned stgB[STAGECAP];
    __shared__ unsigned scA, scB, baseA, baseB;
    __shared__ unsigned s_scan[512];
    __shared__ int s_last;

    int tid = threadIdx.x;
    for (int i = tid; i < NB2; i += blockDim.x) { sa[i] = 0u; sb[i] = 0u; }
    if (tid == 0) { scA = 0u; scB = 0u; }
    __syncthreads();

    unsigned pLo = g_selL1[0];
    unsigned pHi = g_selL1[2];

    int n4 = n >> 2;
    int gstride = gridDim.x * blockDim.x;
    const uint4* d4 = reinterpret_cast<const uint4*>(g_dobs);
    for (int i = blockIdx.x * blockDim.x + tid; i < n4; i += gstride) {
        uint4 v = d4[i];
        #pragma unroll
        for (int k = 0; k < 4; k++) {
            unsigned u = (k == 0) ? v.x : (k == 1) ? v.y : (k == 2) ? v.z : v.w;
            unsigned b = u >> 21;
            if (b == pLo) {
                atomicAdd(&sa[(u >> 9) & 0xFFFu], 1u);
                unsigned p = atomicAdd(&scA, 1u);
                if (p < STAGECAP) stgA[p] = u;
            }
            if (b == pHi) {
                atomicAdd(&sb[(u >> 9) & 0xFFFu], 1u);
                unsigned p = atomicAdd(&scB, 1u);
                if (p < STAGECAP) stgB[p] = u;
            }
        }
    }
    if (blockIdx.x == 0 && tid < (n & 3)) {
        unsigned u = __float_as_uint(g_dobs[(n4 << 2) + tid]);
        unsigned b = u >> 21;
        if (b == pLo) {
            atomicAdd(&sa[(u >> 9) & 0xFFFu], 1u);
            unsigned p = atomicAdd(&scA, 1u);
            if (p < STAGECAP) stgA[p] = u;
        }
        if (b == pHi) {
            atomicAdd(&sb[(u >> 9) & 0xFFFu], 1u);
            unsigned p = atomicAdd(&scB, 1u);
            if (p < STAGECAP) stgB[p] = u;
        }
    }
    __syncthreads();

    for (int i = tid; i < NB2; i += blockDim.x) {
        if (sa[i]) atomicAdd(&g_h2a[i], sa[i]);
        if (sb[i]) atomicAdd(&g_h2b[i], sb[i]);
    }
    unsigned nA = min(scA, (unsigned)STAGECAP);
    unsigned nB = min(scB, (unsigned)STAGECAP);
    if (tid == 0) {
        baseA = atomicAdd(&g_ccA, nA);
        baseB = atomicAdd(&g_ccB, nB);
    }
    __syncthreads();
    for (unsigned i = tid; i < nA; i += blockDim.x) {
        unsigned p = baseA + i;
        if (p < CANDMAX) g_candA[p] = stgA[i];
    }
    for (unsigned i = tid; i < nB; i += blockDim.x) {
        unsigned p = baseB + i;
        if (p < CANDMAX) g_candB[p] = stgB[i];
    }

    // ---- last-block: sel2 ----
    __syncthreads();
    __threadfence();
    if (tid == 0) s_last = (atomicAdd(&g_done2, 1u) == gridDim.x - 1u) ? 1 : 0;
    __syncthreads();
    if (!s_last) return;
    __threadfence();

    sel2_find(g_h2a, g_selL1[1], s_scan, &g_selL2[0]);
    sel2_find(g_h2b, g_selL1[3], s_scan, &g_selL2[2]);

    // leave-clean: reset h2 + done2
    for (int i = tid; i < NB2; i += 512) { g_h2a[i] = 0u; g_h2b[i] = 0u; }
    if (tid == 0) g_done2 = 0u;
}

// ---------------- lvl3 + final: distributed hist, last-block epilogue ------
__device__ unsigned sel3_find(const unsigned* __restrict__ gh, unsigned rank,
                              unsigned* s_scan, unsigned* s_res) {
    int t = threadIdx.x;
    unsigned h0 = gh[2 * t], h1 = gh[2 * t + 1];
    unsigned s = h0 + h1;
    s_scan[t] = s;
    __syncthreads();
    for (int off = 1; off < 256; off <<= 1) {
        unsigned v = (t >= off) ? s_scan[t - off] : 0u;
        __syncthreads();
        s_scan[t] += v;
        __syncthreads();
    }
    unsigned c = s_scan[t] - s;
    if (h0 && rank >= c && rank < c + h0) *s_res = 2u * t;
    c += h0;
    if (h1 && rank >= c && rank < c + h1) *s_res = 2u * t + 1u;
    __syncthreads();
    return *s_res;
}

__global__ void __launch_bounds__(256) lvl3_final_kernel(float* __restrict__ out) {
    __shared__ unsigned h3a[NB3];
    __shared__ unsigned h3b[NB3];
    __shared__ unsigned s_scan[256];
    __shared__ unsigned s_lo, s_hi;
    __shared__ float s_red[24];
    __shared__ int s_last;

    int tid = threadIdx.x;
    for (int i = tid; i < NB3; i += 256) { h3a[i] = 0u; h3b[i] = 0u; }
    __syncthreads();

    unsigned mLo = g_selL2[0];
    unsigned mHi = g_selL2[2];
    unsigned cA = min(g_ccA, (unsigned)CANDMAX);
    unsigned cB = min(g_ccB, (unsigned)CANDMAX);
    unsigned gstride = gridDim.x * 256u;
    for (unsigned i = blockIdx.x * 256u + tid; i < cA; i += gstride) {
        unsigned u = g_candA[i];
        if (((u >> 9) & 0xFFFu) == mLo) atomicAdd(&h3a[u & 0x1FFu], 1u);
    }
    for (unsigned i = blockIdx.x * 256u + tid; i < cB; i += gstride) {
        unsigned u = g_candB[i];
        if (((u >> 9) & 0xFFFu) == mHi) atomicAdd(&h3b[u & 0x1FFu], 1u);
    }
    __syncthreads();
    for (int i = tid; i < NB3; i += 256) {
        if (h3a[i]) atomicAdd(&g_h3a[i], h3a[i]);
        if (h3b[i]) atomicAdd(&g_h3b[i], h3b[i]);
    }

    __syncthreads();
    __threadfence();
    if (tid == 0) s_last = (atomicAdd(&g_done3, 1u) == gridDim.x - 1u) ? 1 : 0;
    __syncthreads();
    if (!s_last) return;
    __threadfence();

    if (tid == 0) { s_lo = 0u; s_hi = 0u; }
    __syncthreads();
    unsigned lo9 = sel3_find(g_h3a, g_selL2[1], s_scan, &s_lo);
    unsigned hi9 = sel3_find(g_h3b, g_selL2[3], s_scan, &s_hi);

    unsigned nv = g_nvalid;
    float ref_dobs;
    if (nv > 0) {
        unsigned uLo = (g_selL1[0] << 21) | (g_selL2[0] << 9) | lo9;
        unsigned uHi = (g_selL1[2] << 21) | (g_selL2[2] << 9) | hi9;
        float vlo = __uint_as_float(uLo);
        float vhi = __uint_as_float(uHi);
        float frac = g_frac;
        float q = vlo * (1.0f - frac) + vhi * frac;
        ref_dobs = fmaxf(q, 1e-6f);
    } else {
        ref_dobs = 1.0f;
    }
    float inv_ref = 1.0f / ref_dobs;

    float nk = 0.0f, sf = 0.0f, sl = 0.0f;
    for (int w = tid; w < NSEG; w += 256) {
        float cnt = g_cnt[w];
        float ps = g_psum[w];
        float rr = g_rate[w] / (CAPACITY + 1e-6f);
        float dm = g_dws[w] / (ps + 1e-6f);
        float bu = fmaxf(rr - 1.0f, 0.0f);
        float flow = bu * bu;
        float rho = fminf(fmaxf(rr, 0.0f), 0.99f);
        float dth = 1.0f / (1.0f - rho + 1e-6f);
        float lat = fmaxf(dth - dm * inv_ref, 0.0f);
        float keep = (cnt >= 2.0f && ps >= 1e-6f) ? 1.0f : 0.0f;
        nk += keep;
        sf += flow * keep;
        sl += lat * keep;
    }
    #pragma unroll
    for (int o = 16; o > 0; o >>= 1) {
        nk += __shfl_down_sync(0xFFFFFFFFu, nk, o);
        sf += __shfl_down_sync(0xFFFFFFFFu, sf, o);
        sl += __shfl_down_sync(0xFFFFFFFFu, sl, o);
    }
    int warp = tid >> 5, lane = tid & 31;
    if (lane == 0) { s_red[warp] = nk; s_red[8 + warp] = sf; s_red[16 + warp] = sl; }
    __syncthreads();
    if (tid == 0) {
        float a = 0.0f, b = 0.0f, c = 0.0f;
        for (int k = 0; k < 8; k++) { a += s_red[k]; b += s_red[8 + k]; c += s_red[16 + k]; }
        float denom = fmaxf(a, 1.0f);
        float l_flow = (a > 0.0f) ? b / denom : 0.0f;
        float l_lat  = (a > 0.0f) ? c / denom : 0.0f;
        float l_data = (float)(g_sum_nllw / g_sum_w);
        out[0] = l_data + ALPHA * l_flow + BETA * l_lat;
        out[1] = l_data;
        out[2] = l_flow;
        out[3] = l_lat;
    }
    __syncthreads();

    // ---- leave-clean: reset everything this pipeline consumed ----
    for (int w = tid; w < NSEG; w += 256) {
        g_cnt[w] = 0.0f; g_psum[w] = 0.0f; g_rate[w] = 0.0f; g_dws[w] = 0.0f;
    }
    for (int i = tid; i < NB3; i += 256) { g_h3a[i] = 0u; g_h3b[i] = 0u; }
    if (tid == 0) {
        g_sum_nllw = 0.0; g_sum_w = 0.0;
        g_ccA = 0u; g_ccB = 0u;
        g_done3 = 0u;
        g_selL1[0] = g_selL1[1] = g_selL1[2] = g_selL1[3] = 0u;
        g_selL2[0] = g_selL2[1] = g_selL2[2] = g_selL2[3] = 0u;
    }
}

// ---------------- launch ----------------
extern "C" void kernel_launch(void* const* d_in, const int* in_sizes, int n_in,
                              void* d_out, int out_size) {
    const float* logits = (const float*)d_in[0];
    const int* y = (const int*)d_in[1];
    const int* mask = (const int*)d_in[2];
    const float* xraw = (const float*)d_in[3];
    const int* widx = (const int*)d_in[4];
    const float* cw = (const float*)d_in[5];
    float* out = (float*)d_out;

    int n = in_sizes[1];
    if (n > NMAX) n = NMAX;

    pass1_kernel<<<444, 512>>>((const float4*)logits, (const int4*)y,
                               (const int4*)mask, xraw, (const int4*)widx, cw, n);
    lvl2_kernel<<<592, 512>>>(n);
    lvl3_final_kernel<<<148, 256>>>(out);
}

// round 11
// speedup vs baseline: 1.1455x; 1.1455x over previous
#include <cuda_runtime.h>

#define NSEG 2048
#define NB1 2048       // level-1: top 11 bits of float pattern
#define NB2 4096       // level-2: bits [20:9]
#define NB3 512        // level-3: bits [8:0]
#define CANDMAX 262144
#define STAGECAP 1024
#define NMAX 4000000

#define ALPHA 0.1f
#define BETA  0.1f
#define CAPACITY 1000.0f

// ---------------- device scratch (zero-init at load; leave-clean protocol:
// every buffer is reset to zero by its LAST consumer each replay) ----------
__device__ double g_sum_nllw;
__device__ double g_sum_w;
__device__ float g_cnt[NSEG];
__device__ float g_psum[NSEG];
__device__ float g_rate[NSEG];
__device__ float g_dws[NSEG];
__device__ unsigned g_h1[NB1];
__device__ unsigned g_h2a[NB2];
__device__ unsigned g_h2b[NB2];
__device__ unsigned g_h3a[NB3];
__device__ unsigned g_h3b[NB3];
__device__ unsigned g_candA[CANDMAX];
__device__ unsigned g_candB[CANDMAX];
__device__ unsigned g_ccA, g_ccB;
__device__ __align__(16) float g_dobs[NMAX];
__device__ unsigned g_selL1[4];   // {bin1Lo, remLo, bin1Hi, remHi}
__device__ unsigned g_selL2[4];   // {mid12Lo, remLo2, mid12Hi, remHi2}
__device__ float g_frac;
__device__ unsigned g_nvalid;
__device__ unsigned g_done1, g_done2, g_done3;

// ---------------- pass1: fused CE + segments + L1-hist + dobs + sel1 -------
// (R8 configuration: pair-wise rows, occ 4, plain float smem atomics)
__global__ void __launch_bounds__(512, 4) pass1_kernel(
    const float4* __restrict__ logits4,
    const int2* __restrict__ y2,
    const int2* __restrict__ m2,
    const float* __restrict__ xraw,
    const int2* __restrict__ w2,
    const float* __restrict__ cw,
    int n)
{
    __shared__ float s_cnt[NSEG];
    __shared__ float s_ps[NSEG];
    __shared__ float s_rt[NSEG];
    __shared__ float s_dw[NSEG];
    __shared__ unsigned s_h1[NB1];
    __shared__ float s_red[32];
    __shared__ unsigned s_scan[512];
    __shared__ float s_totalf;
    __shared__ int s_last;

    int tid = threadIdx.x;
    int lane = tid & 31;
    for (int i = tid; i < NSEG; i += blockDim.x) {
        s_cnt[i] = 0.0f; s_ps[i] = 0.0f; s_rt[i] = 0.0f; s_dw[i] = 0.0f;
        s_h1[i] = 0u;
    }
    __syncthreads();

    const float cw0 = __ldg(&cw[0]);
    const float cw1 = __ldg(&cw[1]);

    float acc_nllw = 0.0f, acc_w = 0.0f;

    int npair = n >> 1;
    int gstride = gridDim.x * blockDim.x;
    for (int j = blockIdx.x * blockDim.x + tid; j < npair; j += gstride) {
        float4 lg = logits4[j];
        int2 yy = y2[j];
        int2 mm = m2[j];
        int2 ww = w2[j];
        int i0 = j * 2;
        float2 xa = *reinterpret_cast<const float2*>(xraw + (size_t)i0 * 8 + 2);
        float2 xb = *reinterpret_cast<const float2*>(xraw + (size_t)(i0 + 1) * 8 + 2);

        // ---- row 0 ----
        float mx0 = fmaxf(lg.x, lg.y);
        float e00 = __expf(lg.x - mx0);
        float e01 = __expf(lg.y - mx0);
        float se0 = e00 + e01;
        float nll0 = mx0 + __logf(se0) - (yy.x ? lg.y : lg.x);
        float wyv0 = (yy.x ? cw1 : cw0) * (mm.x ? 1.0f : 0.0f);
        acc_nllw += nll0 * wyv0;
        acc_w += wyv0;
        float p0 = e01 / se0;
        bool v0 = (mm.x != 0) && (ww.x >= 0);
        float dobs0 = fmaxf(xa.x, 0.0f);
        float rate0 = fmaxf(xa.y, 0.0f);

        // ---- row 1 ----
        float mx1 = fmaxf(lg.z, lg.w);
        float e10 = __expf(lg.z - mx1);
        float e11 = __expf(lg.w - mx1);
        float se1 = e10 + e11;
        float nll1 = mx1 + __logf(se1) - (yy.y ? lg.w : lg.z);
        float wyv1 = (yy.y ? cw1 : cw0) * (mm.y ? 1.0f : 0.0f);
        acc_nllw += nll1 * wyv1;
        acc_w += wyv1;
        float p1 = e11 / se1;
        bool v1 = (mm.y != 0) && (ww.y >= 0);
        float dobs1 = fmaxf(xb.x, 0.0f);
        float rate1 = fmaxf(xb.y, 0.0f);

        float2 st;
        st.x = v0 ? dobs0 : __uint_as_float(0xFFFFFFFFu);
        st.y = v1 ? dobs1 : __uint_as_float(0xFFFFFFFFu);
        *reinterpret_cast<float2*>(&g_dobs[i0]) = st;

        if (v0) {
            atomicAdd(&s_cnt[ww.x], 1.0f);
            atomicAdd(&s_ps[ww.x], p0);
            atomicAdd(&s_rt[ww.x], p0 * rate0);
            atomicAdd(&s_dw[ww.x], p0 * dobs0);
            unsigned ub0 = __float_as_uint(dobs0) >> 21;
            // bin 0 (exact zeros) reconstructed as nvalid - sum(bins>=1)
            if (ub0) atomicAdd(&s_h1[ub0], 1u);
        }
        if (v1) {
            atomicAdd(&s_cnt[ww.y], 1.0f);
            atomicAdd(&s_ps[ww.y], p1);
            atomicAdd(&s_rt[ww.y], p1 * rate1);
            atomicAdd(&s_dw[ww.y], p1 * dobs1);
            unsigned ub1 = __float_as_uint(dobs1) >> 21;
            if (ub1) atomicAdd(&s_h1[ub1], 1u);
        }
    }

    // odd tail row
    if ((n & 1) && blockIdx.x == 0 && tid == 0) {
        int i = n - 1;
        const float* lgs = reinterpret_cast<const float*>(logits4);
        float l0 = lgs[2 * i], l1 = lgs[2 * i + 1];
        int yi = reinterpret_cast<const int*>(y2)[i];
        int m = reinterpret_cast<const int*>(m2)[i];
        int w = reinterpret_cast<const int*>(w2)[i];
        float2 x23 = *reinterpret_cast<const float2*>(xraw + (size_t)i * 8 + 2);
        float mx = fmaxf(l0, l1);
        float e0 = __expf(l0 - mx);
        float e1 = __expf(l1 - mx);
        float se = e0 + e1;
        float nll = mx + __logf(se) - (yi ? l1 : l0);
        float wyv = (yi ? cw1 : cw0) * (m ? 1.0f : 0.0f);
        acc_nllw += nll * wyv;
        acc_w += wyv;
        float p = e1 / se;
        bool valid = (m != 0) && (w >= 0);
        float dobs = fmaxf(x23.x, 0.0f);
        float rate = fmaxf(x23.y, 0.0f);
        if (valid) {
            atomicAdd(&s_cnt[w], 1.0f);
            atomicAdd(&s_ps[w], p);
            atomicAdd(&s_rt[w], p * rate);
            atomicAdd(&s_dw[w], p * dobs);
            unsigned ub = __float_as_uint(dobs) >> 21;
            if (ub) atomicAdd(&s_h1[ub], 1u);
            g_dobs[i] = dobs;
        } else {
            g_dobs[i] = __uint_as_float(0xFFFFFFFFu);
        }
    }

    // CE block reduce
    #pragma unroll
    for (int o = 16; o > 0; o >>= 1) {
        acc_nllw += __shfl_down_sync(0xFFFFFFFFu, acc_nllw, o);
        acc_w    += __shfl_down_sync(0xFFFFFFFFu, acc_w, o);
    }
    int warp = tid >> 5;
    if (lane == 0) { s_red[warp] = acc_nllw; s_red[warp + 16] = acc_w; }
    __syncthreads();
    if (tid == 0) {
        float a = 0.0f, b = 0.0f;
        for (int k = 0; k < 16; k++) { a += s_red[k]; b += s_red[k + 16]; }
        atomicAdd(&g_sum_nllw, (double)a);
        atomicAdd(&g_sum_w, (double)b);
    }

    // flush segment bins + level-1 histogram
    for (int i = tid; i < NSEG; i += blockDim.x) {
        float c = s_cnt[i];
        if (c != 0.0f) {
            atomicAdd(&g_cnt[i], c);
            atomicAdd(&g_psum[i], s_ps[i]);
            atomicAdd(&g_rate[i], s_rt[i]);
            atomicAdd(&g_dws[i], s_dw[i]);
        }
        unsigned h = s_h1[i];
        if (h) atomicAdd(&g_h1[i], h);
    }

    // ---- last-block: sel1 ----
    __syncthreads();
    __threadfence();
    if (tid == 0) s_last = (atomicAdd(&g_done1, 1u) == gridDim.x - 1u) ? 1 : 0;
    __syncthreads();
    if (!s_last) return;
    __threadfence();

    // total valid = sum of g_cnt (exact: integer counts in fp32)
    float csum = 0.0f;
    #pragma unroll
    for (int j = 0; j < 4; j++) csum += g_cnt[tid * 4 + j];
    #pragma unroll
    for (int o = 16; o > 0; o >>= 1) csum += __shfl_down_sync(0xFFFFFFFFu, csum, o);
    if (lane == 0) s_red[warp] = csum;
    __syncthreads();
    if (tid == 0) {
        float t = 0.0f;
        for (int k = 0; k < 16; k++) t += s_red[k];
        s_totalf = t;
    }
    __syncthreads();
    unsigned nvalid = __float2uint_rn(s_totalf);

    // scan of bins >=1 (g_h1[0] is always 0)
    unsigned base = (unsigned)tid * 4;
    unsigned h[4];
    unsigned s = 0;
    #pragma unroll
    for (int j = 0; j < 4; j++) { h[j] = g_h1[base + j]; s += h[j]; }
    // leave-clean: reset h1 for next replay (values held in regs)
    #pragma unroll
    for (int j = 0; j < 4; j++) g_h1[base + j] = 0u;
    s_scan[tid] = s;
    __syncthreads();
    for (int off = 1; off < 512; off <<= 1) {
        unsigned v = (tid >= off) ? s_scan[tid - off] : 0u;
        __syncthreads();
        s_scan[tid] += v;
        __syncthreads();
    }
    unsigned S_rest = s_scan[511];
    unsigned bin0 = nvalid - S_rest;

    float nf = (float)nvalid;
    float pos = fmaxf(0.75f * (nf - 1.0f), 0.0f);
    float fl = floorf(pos);
    unsigned rlo = (unsigned)fl;
    unsigned rhi = (unsigned)ceilf(pos);
    if (tid == 0) {
        g_frac = pos - fl;
        g_nvalid = nvalid;
        g_done1 = 0u;   // leave-clean
        if (nvalid > 0 && rlo < bin0) { g_selL1[0] = 0u; g_selL1[1] = rlo; }
        if (nvalid > 0 && rhi < bin0) { g_selL1[2] = 0u; g_selL1[3] = rhi; }
    }

    unsigned c = bin0 + s_scan[tid] - s;
    #pragma unroll
    for (int j = 0; j < 4; j++) {
        if (h[j]) {
            if (rlo >= c && rlo < c + h[j]) { g_selL1[0] = base + j; g_selL1[1] = rlo - c; }
            if (rhi >= c && rhi < c + h[j]) { g_selL1[2] = base + j; g_selL1[3] = rhi - c; }
        }
        c += h[j];
    }
}

// ---------------- sel2 scan helper (512 threads, 4096 bins) ----------------
__device__ void sel2_find(const unsigned* __restrict__ hist, unsigned rank,
                          unsigned* s_scan, unsigned* gres) {
    int t = threadIdx.x;
    unsigned base = (unsigned)t * 8;
    unsigned h[8];
    unsigned s = 0;
    #pragma unroll
    for (int j = 0; j < 8; j++) { h[j] = hist[base + j]; s += h[j]; }
    s_scan[t] = s;
    __syncthreads();
    for (int off = 1; off < 512; off <<= 1) {
        unsigned v = (t >= off) ? s_scan[t - off] : 0u;
        __syncthreads();
        s_scan[t] += v;
        __syncthreads();
    }
    unsigned c = s_scan[t] - s;
    #pragma unroll
    for (int j = 0; j < 8; j++) {
        if (h[j] && rank >= c && rank < c + h[j]) {
            gres[0] = base + j;
            gres[1] = rank - c;
        }
        c += h[j];
    }
    __syncthreads();
}

// ---------------- lvl2: global hist atomics (sparse) + candidates ----------
// Candidates ~313K of 4M: global atomics over 2x4096 bins are cheap; dropping
// the 32KB smem hist doubles occupancy and removes 8192 init/flush ops/block.
__global__ void __launch_bounds__(512) lvl2_kernel(int n) {
    __shared__ unsigned stgA[STAGECAP];
    __shared__ unsigned stgB[STAGECAP];
    __shared__ unsigned scA, scB, baseA, baseB;
    __shared__ unsigned s_scan[512];
    __shared__ int s_last;

    int tid = threadIdx.x;
    if (tid == 0) { scA = 0u; scB = 0u; }
    __syncthreads();

    unsigned pLo = g_selL1[0];
    unsigned pHi = g_selL1[2];

    int n4 = n >> 2;
    int gstride = gridDim.x * blockDim.x;
    const uint4* d4 = reinterpret_cast<const uint4*>(g_dobs);
    for (int i = blockIdx.x * blockDim.x + tid; i < n4; i += gstride) {
        uint4 v = d4[i];
        #pragma unroll
        for (int k = 0; k < 4; k++) {
            unsigned u = (k == 0) ? v.x : (k == 1) ? v.y : (k == 2) ? v.z : v.w;
            unsigned b = u >> 21;
            if (b == pLo) {
                atomicAdd(&g_h2a[(u >> 9) & 0xFFFu], 1u);
                unsigned p = atomicAdd(&scA, 1u);
                if (p < STAGECAP) stgA[p] = u;
            }
            if (b == pHi) {
                atomicAdd(&g_h2b[(u >> 9) & 0xFFFu], 1u);
                unsigned p = atomicAdd(&scB, 1u);
                if (p < STAGECAP) stgB[p] = u;
            }
        }
    }
    if (blockIdx.x == 0 && tid < (n & 3)) {
        unsigned u = __float_as_uint(g_dobs[(n4 << 2) + tid]);
        unsigned b = u >> 21;
        if (b == pLo) {
            atomicAdd(&g_h2a[(u >> 9) & 0xFFFu], 1u);
            unsigned p = atomicAdd(&scA, 1u);
            if (p < STAGECAP) stgA[p] = u;
        }
        if (b == pHi) {
            atomicAdd(&g_h2b[(u >> 9) & 0xFFFu], 1u);
            unsigned p = atomicAdd(&scB, 1u);
            if (p < STAGECAP) stgB[p] = u;
        }
    }
    __syncthreads();

    unsigned nA = min(scA, (unsigned)STAGECAP);
    unsigned nB = min(scB, (unsigned)STAGECAP);
    if (tid == 0) {
        baseA = atomicAdd(&g_ccA, nA);
        baseB = atomicAdd(&g_ccB, nB);
    }
    __syncthreads();
    for (unsigned i = tid; i < nA; i += blockDim.x) {
        unsigned p = baseA + i;
        if (p < CANDMAX) g_candA[p] = stgA[i];
    }
    for (unsigned i = tid; i < nB; i += blockDim.x) {
        unsigned p = baseB + i;
        if (p < CANDMAX) g_candB[p] = stgB[i];
    }

    // ---- last-block: sel2 ----
    __syncthreads();
    __threadfence();
    if (tid == 0) s_last = (atomicAdd(&g_done2, 1u) == gridDim.x - 1u) ? 1 : 0;
    __syncthreads();
    if (!s_last) return;
    __threadfence();

    sel2_find(g_h2a, g_selL1[1], s_scan, &g_selL2[0]);
    sel2_find(g_h2b, g_selL1[3], s_scan, &g_selL2[2]);

    // leave-clean: reset h2 + done2
    for (int i = tid; i < NB2; i += 512) { g_h2a[i] = 0u; g_h2b[i] = 0u; }
    if (tid == 0) g_done2 = 0u;
}

// ---------------- lvl3 + final: distributed hist, last-block epilogue ------
__device__ unsigned sel3_find(const unsigned* __restrict__ gh, unsigned rank,
                              unsigned* s_scan, unsigned* s_res) {
    int t = threadIdx.x;
    unsigned h0 = gh[2 * t], h1 = gh[2 * t + 1];
    unsigned s = h0 + h1;
    s_scan[t] = s;
    __syncthreads();
    for (int off = 1; off < 256; off <<= 1) {
        unsigned v = (t >= off) ? s_scan[t - off] : 0u;
        __syncthreads();
        s_scan[t] += v;
        __syncthreads();
    }
    unsigned c = s_scan[t] - s;
    if (h0 && rank >= c && rank < c + h0) *s_res = 2u * t;
    c += h0;
    if (h1 && rank >= c && rank < c + h1) *s_res = 2u * t + 1u;
    __syncthreads();
    return *s_res;
}

__global__ void __launch_bounds__(256) lvl3_final_kernel(float* __restrict__ out) {
    __shared__ unsigned h3a[NB3];
    __shared__ unsigned h3b[NB3];
    __shared__ unsigned s_scan[256];
    __shared__ unsigned s_lo, s_hi;
    __shared__ float s_red[24];
    __shared__ int s_last;

    int tid = threadIdx.x;
    for (int i = tid; i < NB3; i += 256) { h3a[i] = 0u; h3b[i] = 0u; }
    __syncthreads();

    unsigned mLo = g_selL2[0];
    unsigned mHi = g_selL2[2];
    unsigned cA = min(g_ccA, (unsigned)CANDMAX);
    unsigned cB = min(g_ccB, (unsigned)CANDMAX);
    unsigned gstride = gridDim.x * 256u;
    for (unsigned i = blockIdx.x * 256u + tid; i < cA; i += gstride) {
        unsigned u = g_candA[i];
        if (((u >> 9) & 0xFFFu) == mLo) atomicAdd(&h3a[u & 0x1FFu], 1u);
    }
    for (unsigned i = blockIdx.x * 256u + tid; i < cB; i += gstride) {
        unsigned u = g_candB[i];
        if (((u >> 9) & 0xFFFu) == mHi) atomicAdd(&h3b[u & 0x1FFu], 1u);
    }
    __syncthreads();
    for (int i = tid; i < NB3; i += 256) {
        if (h3a[i]) atomicAdd(&g_h3a[i], h3a[i]);
        if (h3b[i]) atomicAdd(&g_h3b[i], h3b[i]);
    }

    __syncthreads();
    __threadfence();
    if (tid == 0) s_last = (atomicAdd(&g_done3, 1u) == gridDim.x - 1u) ? 1 : 0;
    __syncthreads();
    if (!s_last) return;
    __threadfence();

    if (tid == 0) { s_lo = 0u; s_hi = 0u; }
    __syncthreads();
    unsigned lo9 = sel3_find(g_h3a, g_selL2[1], s_scan, &s_lo);
    unsigned hi9 = sel3_find(g_h3b, g_selL2[3], s_scan, &s_hi);

    unsigned nv = g_nvalid;
    float ref_dobs;
    if (nv > 0) {
        unsigned uLo = (g_selL1[0] << 21) | (g_selL2[0] << 9) | lo9;
        unsigned uHi = (g_selL1[2] << 21) | (g_selL2[2] << 9) | hi9;
        float vlo = __uint_as_float(uLo);
        float vhi = __uint_as_float(uHi);
        float frac = g_frac;
        float q = vlo * (1.0f - frac) + vhi * frac;
        ref_dobs = fmaxf(q, 1e-6f);
    } else {
        ref_dobs = 1.0f;
    }
    float inv_ref = 1.0f / ref_dobs;

    float nk = 0.0f, sf = 0.0f, sl = 0.0f;
    for (int w = tid; w < NSEG; w += 256) {
        float cnt = g_cnt[w];
        float ps = g_psum[w];
        float rr = g_rate[w] / (CAPACITY + 1e-6f);
        float dm = g_dws[w] / (ps + 1e-6f);
        float bu = fmaxf(rr - 1.0f, 0.0f);
        float flow = bu * bu;
        float rho = fminf(fmaxf(rr, 0.0f), 0.99f);
        float dth = 1.0f / (1.0f - rho + 1e-6f);
        float lat = fmaxf(dth - dm * inv_ref, 0.0f);
        float keep = (cnt >= 2.0f && ps >= 1e-6f) ? 1.0f : 0.0f;
        nk += keep;
        sf += flow * keep;
        sl += lat * keep;
    }
    #pragma unroll
    for (int o = 16; o > 0; o >>= 1) {
        nk += __shfl_down_sync(0xFFFFFFFFu, nk, o);
        sf += __shfl_down_sync(0xFFFFFFFFu, sf, o);
        sl += __shfl_down_sync(0xFFFFFFFFu, sl, o);
    }
    int warp = tid >> 5, lane = tid & 31;
    if (lane == 0) { s_red[warp] = nk; s_red[8 + warp] = sf; s_red[16 + warp] = sl; }
    __syncthreads();
    if (tid == 0) {
        float a = 0.0f, b = 0.0f, c = 0.0f;
        for (int k = 0; k < 8; k++) { a += s_red[k]; b += s_red[8 + k]; c += s_red[16 + k]; }
        float denom = fmaxf(a, 1.0f);
        float l_flow = (a > 0.0f) ? b / denom : 0.0f;
        float l_lat  = (a > 0.0f) ? c / denom : 0.0f;
        float l_data = (float)(g_sum_nllw / g_sum_w);
        out[0] = l_data + ALPHA * l_flow + BETA * l_lat;
        out[1] = l_data;
        out[2] = l_flow;
        out[3] = l_lat;
    }
    __syncthreads();

    // ---- leave-clean: reset everything this pipeline consumed ----
    for (int w = tid; w < NSEG; w += 256) {
        g_cnt[w] = 0.0f; g_psum[w] = 0.0f; g_rate[w] = 0.0f; g_dws[w] = 0.0f;
    }
    for (int i = tid; i < NB3; i += 256) { g_h3a[i] = 0u; g_h3b[i] = 0u; }
    if (tid == 0) {
        g_sum_nllw = 0.0; g_sum_w = 0.0;
        g_ccA = 0u; g_ccB = 0u;
        g_done3 = 0u;
        g_selL1[0] = g_selL1[1] = g_selL1[2] = g_selL1[3] = 0u;
        g_selL2[0] = g_selL2[1] = g_selL2[2] = g_selL2[3] = 0u;
    }
}

// ---------------- launch ----------------
extern "C" void kernel_launch(void* const* d_in, const int* in_sizes, int n_in,
                              void* d_out, int out_size) {
    const float* logits = (const float*)d_in[0];
    const int* y = (const int*)d_in[1];
    const int* mask = (const int*)d_in[2];
    const float* xraw = (const float*)d_in[3];
    const int* widx = (const int*)d_in[4];
    const float* cw = (const float*)d_in[5];
    float* out = (float*)d_out;

    int n = in_sizes[1];
    if (n > NMAX) n = NMAX;

    pass1_kernel<<<592, 512>>>((const float4*)logits, (const int2*)y,
                               (const int2*)mask, xraw, (const int2*)widx, cw, n);
    lvl2_kernel<<<592, 512>>>(n);
    lvl3_final_kernel<<<148, 256>>>(out);
}

// round 13
// speedup vs baseline: 1.1704x; 1.0218x over previous
#include <cuda_runtime.h>

#define NSEG 2048
#define NB1 2048       // level-1: top 11 bits of float pattern
#define NB2 4096       // level-2: bits [20:9]
#define NB3 512        // level-3: bits [8:0]
#define CANDMAX 262144
#define STAGECAP 1024
#define NMAX 4000000

#define ALPHA 0.1f
#define BETA  0.1f
#define CAPACITY 1000.0f

// ---------------- device scratch (zero-init at load; leave-clean protocol:
// every buffer is reset to zero by its LAST consumer each replay) ----------
__device__ double g_sum_nllw;
__device__ double g_sum_w;
__device__ float g_cnt[NSEG];
__device__ float g_psum[NSEG];
__device__ float g_rate[NSEG];
__device__ float g_dws[NSEG];
__device__ unsigned g_h1[NB1];
__device__ unsigned g_h2a[NB2];
__device__ unsigned g_h2b[NB2];
__device__ unsigned g_h3a[NB3];
__device__ unsigned g_h3b[NB3];
__device__ unsigned g_candA[CANDMAX];
__device__ unsigned g_candB[CANDMAX];
__device__ unsigned g_ccA, g_ccB;
__device__ __align__(16) float g_dobs[NMAX];
__device__ unsigned g_selL1[4];   // {bin1Lo, remLo, bin1Hi, remHi}
__device__ unsigned g_selL2[4];   // {mid12Lo, remLo2, mid12Hi, remHi2}
__device__ float g_frac;
__device__ unsigned g_nvalid;
__device__ unsigned g_done1, g_done2, g_done3;

// ---------------- pass1: fused CE + segments + L1-hist + dobs + sel1 -------
// 1 row/thread: x_raw read as ONE float4 (cols 0-3, 32B stride) halves the
// L1 wavefronts of the previous two 64B-stride float2 gathers; logits are a
// contiguous float2, y/m/w scalar ints, dobs store scalar. L1-pipe work per
// row drops ~25% while DRAM bytes stay at the 224MB sector floor.
__global__ void __launch_bounds__(512, 4) pass1_kernel(
    const float2* __restrict__ logits2,
    const int* __restrict__ y,
    const int* __restrict__ mask,
    const float4* __restrict__ xraw4,
    const int* __restrict__ widx,
    const float* __restrict__ cw,
    int n)
{
    __shared__ float s_cnt[NSEG];
    __shared__ float s_ps[NSEG];
    __shared__ float s_rt[NSEG];
    __shared__ float s_dw[NSEG];
    __shared__ unsigned s_h1[NB1];
    __shared__ float s_red[32];
    __shared__ unsigned s_scan[512];
    __shared__ float s_totalf;
    __shared__ int s_last;

    int tid = threadIdx.x;
    int lane = tid & 31;
    for (int i = tid; i < NSEG; i += blockDim.x) {
        s_cnt[i] = 0.0f; s_ps[i] = 0.0f; s_rt[i] = 0.0f; s_dw[i] = 0.0f;
        s_h1[i] = 0u;
    }
    __syncthreads();

    const float cw0 = __ldg(&cw[0]);
    const float cw1 = __ldg(&cw[1]);

    float acc_nllw = 0.0f, acc_w = 0.0f;

    int gstride = gridDim.x * blockDim.x;
    for (int i = blockIdx.x * blockDim.x + tid; i < n; i += gstride) {
        float2 lg = logits2[i];
        int yi = y[i];
        int m = mask[i];
        int w = widx[i];
        float4 xr = xraw4[2 * i];   // row i cols 0-3; .z = d_obs, .w = rate

        float mx = fmaxf(lg.x, lg.y);
        float e0 = __expf(lg.x - mx);
        float e1 = __expf(lg.y - mx);
        float se = e0 + e1;
        float nll = mx + __logf(se) - (yi ? lg.y : lg.x);
        float wyv = (yi ? cw1 : cw0) * (m ? 1.0f : 0.0f);
        acc_nllw += nll * wyv;
        acc_w += wyv;
        float p = e1 / se;
        bool valid = (m != 0) && (w >= 0);
        float dobs = fmaxf(xr.z, 0.0f);
        float rate = fmaxf(xr.w, 0.0f);

        g_dobs[i] = valid ? dobs : __uint_as_float(0xFFFFFFFFu);

        if (valid) {
            atomicAdd(&s_cnt[w], 1.0f);
            atomicAdd(&s_ps[w], p);
            atomicAdd(&s_rt[w], p * rate);
            atomicAdd(&s_dw[w], p * dobs);
            unsigned ub = __float_as_uint(dobs) >> 21;
            // bin 0 (exact zeros) reconstructed as nvalid - sum(bins>=1)
            if (ub) atomicAdd(&s_h1[ub], 1u);
        }
    }

    // CE block reduce
    #pragma unroll
    for (int o = 16; o > 0; o >>= 1) {
        acc_nllw += __shfl_down_sync(0xFFFFFFFFu, acc_nllw, o);
        acc_w    += __shfl_down_sync(0xFFFFFFFFu, acc_w, o);
    }
    int warp = tid >> 5;
    if (lane == 0) { s_red[warp] = acc_nllw; s_red[warp + 16] = acc_w; }
    __syncthreads();
    if (tid == 0) {
        float a = 0.0f, b = 0.0f;
        for (int k = 0; k < 16; k++) { a += s_red[k]; b += s_red[k + 16]; }
        atomicAdd(&g_sum_nllw, (double)a);
        atomicAdd(&g_sum_w, (double)b);
    }

    // flush segment bins + level-1 histogram
    for (int i = tid; i < NSEG; i += blockDim.x) {
        float c = s_cnt[i];
        if (c != 0.0f) {
            atomicAdd(&g_cnt[i], c);
            atomicAdd(&g_psum[i], s_ps[i]);
            atomicAdd(&g_rate[i], s_rt[i]);
            atomicAdd(&g_dws[i], s_dw[i]);
        }
        unsigned h = s_h1[i];
        if (h) atomicAdd(&g_h1[i], h);
    }

    // ---- last-block: sel1 ----
    __syncthreads();
    __threadfence();
    if (tid == 0) s_last = (atomicAdd(&g_done1, 1u) == gridDim.x - 1u) ? 1 : 0;
    __syncthreads();
    if (!s_last) return;
    __threadfence();

    // total valid = sum of g_cnt (exact: integer counts in fp32)
    float csum = 0.0f;
    #pragma unroll
    for (int j = 0; j < 4; j++) csum += g_cnt[tid * 4 + j];
    #pragma unroll
    for (int o = 16; o > 0; o >>= 1) csum += __shfl_down_sync(0xFFFFFFFFu, csum, o);
    if (lane == 0) s_red[warp] = csum;
    __syncthreads();
    if (tid == 0) {
        float t = 0.0f;
        for (int k = 0; k < 16; k++) t += s_red[k];
        s_totalf = t;
    }
    __syncthreads();
    unsigned nvalid = __float2uint_rn(s_totalf);

    // scan of bins >=1 (g_h1[0] is always 0)
    unsigned base = (unsigned)tid * 4;
    unsigned h[4];
    unsigned s = 0;
    #pragma unroll
    for (int j = 0; j < 4; j++) { h[j] = g_h1[base + j]; s += h[j]; }
    // leave-clean: reset h1 for next replay (values held in regs)
    #pragma unroll
    for (int j = 0; j < 4; j++) g_h1[base + j] = 0u;
    s_scan[tid] = s;
    __syncthreads();
    for (int off = 1; off < 512; off <<= 1) {
        unsigned v = (tid >= off) ? s_scan[tid - off] : 0u;
        __syncthreads();
        s_scan[tid] += v;
        __syncthreads();
    }
    unsigned S_rest = s_scan[511];
    unsigned bin0 = nvalid - S_rest;

    float nf = (float)nvalid;
    float pos = fmaxf(0.75f * (nf - 1.0f), 0.0f);
    float fl = floorf(pos);
    unsigned rlo = (unsigned)fl;
    unsigned rhi = (unsigned)ceilf(pos);
    if (tid == 0) {
        g_frac = pos - fl;
        g_nvalid = nvalid;
        g_done1 = 0u;   // leave-clean
        if (nvalid > 0 && rlo < bin0) { g_selL1[0] = 0u; g_selL1[1] = rlo; }
        if (nvalid > 0 && rhi < bin0) { g_selL1[2] = 0u; g_selL1[3] = rhi; }
    }

    unsigned c = bin0 + s_scan[tid] - s;
    #pragma unroll
    for (int j = 0; j < 4; j++) {
        if (h[j]) {
            if (rlo >= c && rlo < c + h[j]) { g_selL1[0] = base + j; g_selL1[1] = rlo - c; }
            if (rhi >= c && rhi < c + h[j]) { g_selL1[2] = base + j; g_selL1[3] = rhi - c; }
        }
        c += h[j];
    }
}

// ---------------- sel2 scan helper (512 threads, 4096 bins) ----------------
__device__ void sel2_find(const unsigned* __restrict__ hist, unsigned rank,
                          unsigned* s_scan, unsigned* gres) {
    int t = threadIdx.x;
    unsigned base = (unsigned)t * 8;
    unsigned h[8];
    unsigned s = 0;
    #pragma unroll
    for (int j = 0; j < 8; j++) { h[j] = hist[base + j]; s += h[j]; }
    s_scan[t] = s;
    __syncthreads();
    for (int off = 1; off < 512; off <<= 1) {
        unsigned v = (t >= off) ? s_scan[t - off] : 0u;
        __syncthreads();
        s_scan[t] += v;
        __syncthreads();
    }
    unsigned c = s_scan[t] - s;
    #pragma unroll
    for (int j = 0; j < 8; j++) {
        if (h[j] && rank >= c && rank < c + h[j]) {
            gres[0] = base + j;
            gres[1] = rank - c;
        }
        c += h[j];
    }
    __syncthreads();
}

// ---------------- lvl2: global hist atomics (sparse) + candidates ----------
__global__ void __launch_bounds__(512) lvl2_kernel(int n) {
    __shared__ unsigned stgA[STAGECAP];
    __shared__ unsigned stgB[STAGECAP];
    __shared__ unsigned scA, scB, baseA, baseB;
    __shared__ unsigned s_scan[512];
    __shared__ int s_last;

    int tid = threadIdx.x;
    if (tid == 0) { scA = 0u; scB = 0u; }
    __syncthreads();

    unsigned pLo = g_selL1[0];
    unsigned pHi = g_selL1[2];

    int n4 = n >> 2;
    int gstride = gridDim.x * blockDim.x;
    const uint4* d4 = reinterpret_cast<const uint4*>(g_dobs);
    for (int i = blockIdx.x * blockDim.x + tid; i < n4; i += gstride) {
        uint4 v = d4[i];
        #pragma unroll
        for (int k = 0; k < 4; k++) {
            unsigned u = (k == 0) ? v.x : (k == 1) ? v.y : (k == 2) ? v.z : v.w;
            unsigned b = u >> 21;
            if (b == pLo) {
                atomicAdd(&g_h2a[(u >> 9) & 0xFFFu], 1u);
                unsigned p = atomicAdd(&scA, 1u);
                if (p < STAGECAP) stgA[p] = u;
            }
            if (b == pHi) {
                atomicAdd(&g_h2b[(u >> 9) & 0xFFFu], 1u);
                unsigned p = atomicAdd(&scB, 1u);
                if (p < STAGECAP) stgB[p] = u;
            }
        }
    }
    if (blockIdx.x == 0 && tid < (n & 3)) {
        unsigned u = __float_as_uint(g_dobs[(n4 << 2) + tid]);
        unsigned b = u >> 21;
        if (b == pLo) {
            atomicAdd(&g_h2a[(u >> 9) & 0xFFFu], 1u);
            unsigned p = atomicAdd(&scA, 1u);
            if (p < STAGECAP) stgA[p] = u;
        }
        if (b == pHi) {
            atomicAdd(&g_h2b[(u >> 9) & 0xFFFu], 1u);
            unsigned p = atomicAdd(&scB, 1u);
            if (p < STAGECAP) stgB[p] = u;
        }
    }
    __syncthreads();

    unsigned nA = min(scA, (unsigned)STAGECAP);
    unsigned nB = min(scB, (unsigned)STAGECAP);
    if (tid == 0) {
        baseA = atomicAdd(&g_ccA, nA);
        baseB = atomicAdd(&g_ccB, nB);
    }
    __syncthreads();
    for (unsigned i = tid; i < nA; i += blockDim.x) {
        unsigned p = baseA + i;
        if (p < CANDMAX) g_candA[p] = stgA[i];
    }
    for (unsigned i = tid; i < nB; i += blockDim.x) {
        unsigned p = baseB + i;
        if (p < CANDMAX) g_candB[p] = stgB[i];
    }

    // ---- last-block: sel2 ----
    __syncthreads();
    __threadfence();
    if (tid == 0) s_last = (atomicAdd(&g_done2, 1u) == gridDim.x - 1u) ? 1 : 0;
    __syncthreads();
    if (!s_last) return;
    __threadfence();

    sel2_find(g_h2a, g_selL1[1], s_scan, &g_selL2[0]);
    sel2_find(g_h2b, g_selL1[3], s_scan, &g_selL2[2]);

    // leave-clean: reset h2 + done2
    for (int i = tid; i < NB2; i += 512) { g_h2a[i] = 0u; g_h2b[i] = 0u; }
    if (tid == 0) g_done2 = 0u;
}

// ---------------- lvl3 + final: distributed hist, last-block epilogue ------
__device__ unsigned sel3_find(const unsigned* __restrict__ gh, unsigned rank,
                              unsigned* s_scan, unsigned* s_res) {
    int t = threadIdx.x;
    unsigned h0 = gh[2 * t], h1 = gh[2 * t + 1];
    unsigned s = h0 + h1;
    s_scan[t] = s;
    __syncthreads();
    for (int off = 1; off < 256; off <<= 1) {
        unsigned v = (t >= off) ? s_scan[t - off] : 0u;
        __syncthreads();
        s_scan[t] += v;
        __syncthreads();
    }
    unsigned c = s_scan[t] - s;
    if (h0 && rank >= c && rank < c + h0) *s_res = 2u * t;
    c += h0;
    if (h1 && rank >= c && rank < c + h1) *s_res = 2u * t + 1u;
    __syncthreads();
    return *s_res;
}

__global__ void __launch_bounds__(256) lvl3_final_kernel(float* __restrict__ out) {
    __shared__ unsigned h3a[NB3];
    __shared__ unsigned h3b[NB3];
    __shared__ unsigned s_scan[256];
    __shared__ unsigned s_lo, s_hi;
    __shared__ float s_red[24];
    __shared__ int s_last;

    int tid = threadIdx.x;
    for (int i = tid; i < NB3; i += 256) { h3a[i] = 0u; h3b[i] = 0u; }
    __syncthreads();

    unsigned mLo = g_selL2[0];
    unsigned mHi = g_selL2[2];
    unsigned cA = min(g_ccA, (unsigned)CANDMAX);
    unsigned cB = min(g_ccB, (unsigned)CANDMAX);
    unsigned gstride = gridDim.x * 256u;
    for (unsigned i = blockIdx.x * 256u + tid; i < cA; i += gstride) {
        unsigned u = g_candA[i];
        if (((u >> 9) & 0xFFFu) == mLo) atomicAdd(&h3a[u & 0x1FFu], 1u);
    }
    for (unsigned i = blockIdx.x * 256u + tid; i < cB; i += gstride) {
        unsigned u = g_candB[i];
        if (((u >> 9) & 0xFFFu) == mHi) atomicAdd(&h3b[u & 0x1FFu], 1u);
    }
    __syncthreads();
    for (int i = tid; i < NB3; i += 256) {
        if (h3a[i]) atomicAdd(&g_h3a[i], h3a[i]);
        if (h3b[i]) atomicAdd(&g_h3b[i], h3b[i]);
    }

    __syncthreads();
    __threadfence();
    if (tid == 0) s_last = (atomicAdd(&g_done3, 1u) == gridDim.x - 1u) ? 1 : 0;
    __syncthreads();
    if (!s_last) return;
    __threadfence();

    if (tid == 0) { s_lo = 0u; s_hi = 0u; }
    __syncthreads();
    unsigned lo9 = sel3_find(g_h3a, g_selL2[1], s_scan, &s_lo);
    unsigned hi9 = sel3_find(g_h3b, g_selL2[3], s_scan, &s_hi);

    unsigned nv = g_nvalid;
    float ref_dobs;
    if (nv > 0) {
        unsigned uLo = (g_selL1[0] << 21) | (g_selL2[0] << 9) | lo9;
        unsigned uHi = (g_selL1[2] << 21) | (g_selL2[2] << 9) | hi9;
        float vlo = __uint_as_float(uLo);
        float vhi = __uint_as_float(uHi);
        float frac = g_frac;
        float q = vlo * (1.0f - frac) + vhi * frac;
        ref_dobs = fmaxf(q, 1e-6f);
    } else {
        ref_dobs = 1.0f;
    }
    float inv_ref = 1.0f / ref_dobs;

    float nk = 0.0f, sf = 0.0f, sl = 0.0f;
    for (int w = tid; w < NSEG; w += 256) {
        float cnt = g_cnt[w];
        float ps = g_psum[w];
        float rr = g_rate[w] / (CAPACITY + 1e-6f);
        float dm = g_dws[w] / (ps + 1e-6f);
        float bu = fmaxf(rr - 1.0f, 0.0f);
        float flow = bu * bu;
        float rho = fminf(fmaxf(rr, 0.0f), 0.99f);
        float dth = 1.0f / (1.0f - rho + 1e-6f);
        float lat = fmaxf(dth - dm * inv_ref, 0.0f);
        float keep = (cnt >= 2.0f && ps >= 1e-6f) ? 1.0f : 0.0f;
        nk += keep;
        sf += flow * keep;
        sl += lat * keep;
    }
    #pragma unroll
    for (int o = 16; o > 0; o >>= 1) {
        nk += __shfl_down_sync(0xFFFFFFFFu, nk, o);
        sf += __shfl_down_sync(0xFFFFFFFFu, sf, o);
        sl += __shfl_down_sync(0xFFFFFFFFu, sl, o);
    }
    int warp = tid >> 5, lane = tid & 31;
    if (lane == 0) { s_red[warp] = nk; s_red[8 + warp] = sf; s_red[16 + warp] = sl; }
    __syncthreads();
    if (tid == 0) {
        float a = 0.0f, b = 0.0f, c = 0.0f;
        for (int k = 0; k < 8; k++) { a += s_red[k]; b += s_red[8 + k]; c += s_red[16 + k]; }
        float denom = fmaxf(a, 1.0f);
        float l_flow = (a > 0.0f) ? b / denom : 0.0f;
        float l_lat  = (a > 0.0f) ? c / denom : 0.0f;
        float l_data = (float)(g_sum_nllw / g_sum_w);
        out[0] = l_data + ALPHA * l_flow + BETA * l_lat;
        out[1] = l_data;
        out[2] = l_flow;
        out[3] = l_lat;
    }
    __syncthreads();

    // ---- leave-clean: reset everything this pipeline consumed ----
    for (int w = tid; w < NSEG; w += 256) {
        g_cnt[w] = 0.0f; g_psum[w] = 0.0f; g_rate[w] = 0.0f; g_dws[w] = 0.0f;
    }
    for (int i = tid; i < NB3; i += 256) { g_h3a[i] = 0u; g_h3b[i] = 0u; }
    if (tid == 0) {
        g_sum_nllw = 0.0; g_sum_w = 0.0;
        g_ccA = 0u; g_ccB = 0u;
        g_done3 = 0u;
        g_selL1[0] = g_selL1[1] = g_selL1[2] = g_selL1[3] = 0u;
        g_selL2[0] = g_selL2[1] = g_selL2[2] = g_selL2[3] = 0u;
    }
}

// ---------------- launch ----------------
extern "C" void kernel_launch(void* const* d_in, const int* in_sizes, int n_in,
                              void* d_out, int out_size) {
    const float* logits = (const float*)d_in[0];
    const int* y = (const int*)d_in[1];
    const int* mask = (const int*)d_in[2];
    const float* xraw = (const float*)d_in[3];
    const int* widx = (const int*)d_in[4];
    const float* cw = (const float*)d_in[5];
    float* out = (float*)d_out;

    int n = in_sizes[1];
    if (n > NMAX) n = NMAX;

    pass1_kernel<<<592, 512>>>((const float2*)logits, y, mask,
                               (const float4*)xraw, widx, cw, n);
    lvl2_kernel<<<592, 512>>>(n);
    lvl3_final_kernel<<<148, 256>>>(out);
}